// round 3
// baseline (speedup 1.0000x reference)
#include <cuda_runtime.h>

#define N_NODES 50000
#define D 128
#define N_EDGES 800000

// ---------------- scratch (device globals: no allocation allowed) ----------
__device__ __align__(16) float g_msg[N_NODES * D];  // aggregation buffer
__device__ __align__(16) float g_h[N_NODES * D];    // layer-1 activation
__device__ float g_rinv_out[N_NODES];
__device__ float g_rinv_in[N_NODES];
__device__ int   g_deg_out[N_NODES];
__device__ int   g_deg_in[N_NODES];

// ---------------- kernels --------------------------------------------------

__global__ void zero_deg_kernel() {
    int i = blockIdx.x * blockDim.x + threadIdx.x;
    if (i < N_NODES) { g_deg_out[i] = 0; g_deg_in[i] = 0; }
}

// NOTE: indices are int32 (JAX x64 disabled => jnp.int64 request yields int32)
__global__ void deg_kernel(const int* __restrict__ src,
                           const int* __restrict__ dst) {
    int e = blockIdx.x * blockDim.x + threadIdx.x;
    if (e < N_EDGES) {
        atomicAdd(&g_deg_out[src[e]], 1);
        atomicAdd(&g_deg_in[dst[e]], 1);
    }
}

__global__ void rinv_kernel() {
    int i = blockIdx.x * blockDim.x + threadIdx.x;
    if (i < N_NODES) {
        g_rinv_out[i] = rsqrtf((float)max(g_deg_out[i], 1));
        g_rinv_in[i]  = rsqrtf((float)max(g_deg_in[i], 1));
    }
}

__global__ void zero_msg_kernel() {
    int i = blockIdx.x * blockDim.x + threadIdx.x;   // float4 index
    const int n4 = N_NODES * D / 4;
    if (i < n4) ((float4*)g_msg)[i] = make_float4(0.f, 0.f, 0.f, 0.f);
}

// one warp per edge: gather 128 floats of input[src], scale by rsqrt(deg_out[src]),
// vector-atomic add into g_msg[dst]. FROM_H selects g_h as input.
template <bool FROM_H>
__global__ void scatter_kernel(const float* __restrict__ xin,
                               const int* __restrict__ src,
                               const int* __restrict__ dst) {
    int gtid = blockIdx.x * blockDim.x + threadIdx.x;
    int e = gtid >> 5;
    int lane = gtid & 31;
    if (e >= N_EDGES) return;
    int s = src[e];
    int d = dst[e];
    const float* in = FROM_H ? (const float*)g_h : xin;
    float scale = g_rinv_out[s];
    float4 v = ((const float4*)(in + (size_t)s * D))[lane];
    float* mr = g_msg + (size_t)d * D + lane * 4;
    // red.global.add.v4.f32: one 16B L2 RMW instead of 4 scalar atomics (sm_90+)
    asm volatile("red.global.add.v4.f32 [%0], {%1, %2, %3, %4};"
                 :: "l"(mr), "f"(v.x * scale), "f"(v.y * scale),
                    "f"(v.z * scale), "f"(v.w * scale)
                 : "memory");
}

// out[row] = (g_msg[row] * rinv_in[row]) @ W + b   (optional relu)
// Block: 256 threads, 32 rows per block. Static smem only (48 KB):
//   sW:  [64][128] = 32 KB  (one K-chunk of W at a time, 2 chunks)
//   sIn: [32][128] = 16 KB  (pre-scaled input tile)
// TO_H: write to g_h (layer 1); else write to outp (layer 2).
template <bool RELU, bool TO_H>
__global__ void gemm_kernel(const float* __restrict__ W,
                            const float* __restrict__ b,
                            float* __restrict__ outp) {
    __shared__ float sW[64 * D];
    __shared__ float sIn[32 * D];

    int tid = threadIdx.x;
    int rowBase = blockIdx.x * 32;
    float* out = TO_H ? (float*)g_h : outp;

    // cooperative load of the 32x128 input tile, scaled; guard rows >= N
    float4* sIn4 = (float4*)sIn;
    #pragma unroll
    for (int i = 0; i < 4; i++) {
        int idx = tid + 256 * i;           // float4 index within tile
        int lr = idx >> 5;                 // local row (32 float4 per row)
        int row = rowBase + lr;
        float4 v = make_float4(0.f, 0.f, 0.f, 0.f);
        if (row < N_NODES) {
            float rs = g_rinv_in[row];
            float4 m = ((const float4*)(g_msg + (size_t)row * D))[idx & 31];
            v = make_float4(m.x * rs, m.y * rs, m.z * rs, m.w * rs);
        }
        sIn4[idx] = v;
    }

    int ty = tid >> 5;                 // 0..7  -> 4 rows each
    int col0 = (tid & 31) * 4;         // 4 cols each
    int lr0 = ty * 4;

    float acc[4][4];
    float4 bv = *(const float4*)(b + col0);
    #pragma unroll
    for (int r = 0; r < 4; r++) {
        acc[r][0] = bv.x; acc[r][1] = bv.y; acc[r][2] = bv.z; acc[r][3] = bv.w;
    }

    const float4* W4 = (const float4*)W;
    float4* sW4 = (float4*)sW;

    #pragma unroll
    for (int kc = 0; kc < 2; kc++) {
        __syncthreads();   // protect sW reuse (and first-iter sIn visibility)
        // load W rows [kc*64, kc*64+64): 64*128/4 = 2048 float4, 8 per thread
        #pragma unroll
        for (int i = 0; i < 8; i++)
            sW4[tid + 256 * i] = W4[kc * 2048 + tid + 256 * i];
        __syncthreads();

        #pragma unroll 4
        for (int k = 0; k < 64; k++) {
            float4 w = *(const float4*)(sW + k * D + col0);
            #pragma unroll
            for (int r = 0; r < 4; r++) {
                float a = sIn[(lr0 + r) * D + kc * 64 + k];
                acc[r][0] = fmaf(a, w.x, acc[r][0]);
                acc[r][1] = fmaf(a, w.y, acc[r][1]);
                acc[r][2] = fmaf(a, w.z, acc[r][2]);
                acc[r][3] = fmaf(a, w.w, acc[r][3]);
            }
        }
    }

    #pragma unroll
    for (int r = 0; r < 4; r++) {
        int row = rowBase + lr0 + r;
        if (row < N_NODES) {
            float4 o;
            if (RELU) {
                o = make_float4(fmaxf(acc[r][0], 0.f), fmaxf(acc[r][1], 0.f),
                                fmaxf(acc[r][2], 0.f), fmaxf(acc[r][3], 0.f));
            } else {
                o = make_float4(acc[r][0], acc[r][1], acc[r][2], acc[r][3]);
            }
            *(float4*)(out + (size_t)row * D + col0) = o;
        }
    }
}

// ---------------- launch ----------------------------------------------------
// Launches ONLY — no runtime API calls (graph-capture safe).

extern "C" void kernel_launch(void* const* d_in, const int* in_sizes, int n_in,
                              void* d_out, int out_size) {
    const float* x   = (const float*)d_in[0];
    const int*   src = (const int*)d_in[1];
    const int*   dst = (const int*)d_in[2];
    const float* W1  = (const float*)d_in[3];
    const float* b1  = (const float*)d_in[4];
    const float* W2  = (const float*)d_in[5];
    const float* b2  = (const float*)d_in[6];
    float* out = (float*)d_out;

    const int T = 256;
    int nodeBlocks = (N_NODES + T - 1) / T;
    int edgeBlocks = (N_EDGES + T - 1) / T;
    int msg4Blocks = (N_NODES * D / 4 + T - 1) / T;
    int scatBlocks = (int)(((long long)N_EDGES * 32 + T - 1) / T);
    int gemmBlocks = (N_NODES + 31) / 32;

    // degrees (shared across both layers)
    zero_deg_kernel<<<nodeBlocks, T>>>();
    deg_kernel<<<edgeBlocks, T>>>(src, dst);
    rinv_kernel<<<nodeBlocks, T>>>();

    // layer 1: msg = scatter(x); h = relu(msg*rinv_in @ W1 + b1)
    zero_msg_kernel<<<msg4Blocks, T>>>();
    scatter_kernel<false><<<scatBlocks, T>>>(x, src, dst);
    gemm_kernel<true, true><<<gemmBlocks, T>>>(W1, b1, nullptr);

    // layer 2: msg = scatter(h); out = msg*rinv_in @ W2 + b2
    zero_msg_kernel<<<msg4Blocks, T>>>();
    scatter_kernel<true><<<scatBlocks, T>>>(nullptr, src, dst);
    gemm_kernel<false, false><<<gemmBlocks, T>>>(W2, b2, out);
}

// round 5
// speedup vs baseline: 1.1253x; 1.1253x over previous
#include <cuda_runtime.h>

#define N_NODES 50000
#define D 128
#define N_EDGES 800000

// ---------------- scratch (device globals: no allocation allowed) ----------
__device__ __align__(16) float g_msg[N_NODES * D];  // aggregated (rinv_in-scaled)
__device__ __align__(16) float g_h[N_NODES * D];    // layer-1 act (rinv_out-scaled)
__device__ float g_rinv_out[N_NODES];
__device__ float g_rinv_in[N_NODES];
__device__ int   g_deg_out[N_NODES];
__device__ int   g_deg_in[N_NODES];
__device__ int   g_off[N_NODES + 1];                // CSR row offsets (by dst)
__device__ int   g_cur[N_NODES];                    // fill cursors
__device__ int   g_esrc[N_EDGES];                   // src ids bucketed by dst

// ---------------- graph preprocessing --------------------------------------

__global__ void zero_deg_kernel() {
    int i = blockIdx.x * blockDim.x + threadIdx.x;
    if (i < N_NODES) { g_deg_out[i] = 0; g_deg_in[i] = 0; }
}

// NOTE: indices are int32 (JAX x64 disabled => int32 despite jnp.int64 request)
__global__ void deg_kernel(const int* __restrict__ src,
                           const int* __restrict__ dst) {
    int e = blockIdx.x * blockDim.x + threadIdx.x;
    if (e < N_EDGES) {
        atomicAdd(&g_deg_out[src[e]], 1);
        atomicAdd(&g_deg_in[dst[e]], 1);
    }
}

__global__ void rinv_kernel() {
    int i = blockIdx.x * blockDim.x + threadIdx.x;
    if (i < N_NODES) {
        g_rinv_out[i] = rsqrtf((float)max(g_deg_out[i], 1));
        g_rinv_in[i]  = rsqrtf((float)max(g_deg_in[i], 1));
    }
}

// single-block exclusive scan of g_deg_in -> g_off / g_cur
__global__ void scan_kernel() {
    __shared__ int s[1024];
    const int t = threadIdx.x;
    const int CH = (N_NODES + 1023) / 1024;       // 49
    int beg = t * CH;
    int end = min(beg + CH, N_NODES);
    int sum = 0;
    for (int i = beg; i < end; i++) sum += g_deg_in[i];
    s[t] = sum;
    __syncthreads();
    // Hillis-Steele inclusive scan over 1024 partials
    for (int d = 1; d < 1024; d <<= 1) {
        int v = (t >= d) ? s[t - d] : 0;
        __syncthreads();
        s[t] += v;
        __syncthreads();
    }
    int run = s[t] - sum;                          // exclusive prefix of chunk
    for (int i = beg; i < end; i++) {
        g_off[i] = run;
        g_cur[i] = run;
        run += g_deg_in[i];
    }
    if (t == 1023) g_off[N_NODES] = run;           // == N_EDGES
}

__global__ void fill_kernel(const int* __restrict__ src,
                            const int* __restrict__ dst) {
    int e = blockIdx.x * blockDim.x + threadIdx.x;
    if (e < N_EDGES) {
        int pos = atomicAdd(&g_cur[dst[e]], 1);
        g_esrc[pos] = src[e];
    }
}

// ---------------- aggregation: one warp per node ----------------------------
// msg[v] = rinv_in[v] * sum_{e: dst=v} scale_e * in[src_e]
// Layer 1 (FROM_H=false): in = xin (harness pointer), scale_e = rinv_out[src_e]
// Layer 2 (FROM_H=true):  in = g_h (already rinv_out-scaled), scale_e = 1
template <bool FROM_H>
__global__ void agg_kernel(const float* __restrict__ xin) {
    int gtid = blockIdx.x * blockDim.x + threadIdx.x;
    int v = gtid >> 5;
    int lane = gtid & 31;
    if (v >= N_NODES) return;
    const float* in = FROM_H ? (const float*)g_h : xin;

    int beg = g_off[v], end = g_off[v + 1];
    float ax = 0.f, ay = 0.f, az = 0.f, aw = 0.f;

    int i = beg;
    for (; i + 4 <= end; i += 4) {
        int s0 = g_esrc[i + 0];
        int s1 = g_esrc[i + 1];
        int s2 = g_esrc[i + 2];
        int s3 = g_esrc[i + 3];
        float4 v0 = ((const float4*)(in + (size_t)s0 * D))[lane];
        float4 v1 = ((const float4*)(in + (size_t)s1 * D))[lane];
        float4 v2 = ((const float4*)(in + (size_t)s2 * D))[lane];
        float4 v3 = ((const float4*)(in + (size_t)s3 * D))[lane];
        if (!FROM_H) {
            float c0 = g_rinv_out[s0], c1 = g_rinv_out[s1];
            float c2 = g_rinv_out[s2], c3 = g_rinv_out[s3];
            ax = fmaf(v0.x, c0, fmaf(v1.x, c1, fmaf(v2.x, c2, fmaf(v3.x, c3, ax))));
            ay = fmaf(v0.y, c0, fmaf(v1.y, c1, fmaf(v2.y, c2, fmaf(v3.y, c3, ay))));
            az = fmaf(v0.z, c0, fmaf(v1.z, c1, fmaf(v2.z, c2, fmaf(v3.z, c3, az))));
            aw = fmaf(v0.w, c0, fmaf(v1.w, c1, fmaf(v2.w, c2, fmaf(v3.w, c3, aw))));
        } else {
            ax += v0.x + v1.x + v2.x + v3.x;
            ay += v0.y + v1.y + v2.y + v3.y;
            az += v0.z + v1.z + v2.z + v3.z;
            aw += v0.w + v1.w + v2.w + v3.w;
        }
    }
    for (; i < end; i++) {
        int s = g_esrc[i];
        float4 vv = ((const float4*)(in + (size_t)s * D))[lane];
        float c = FROM_H ? 1.f : g_rinv_out[s];
        ax = fmaf(vv.x, c, ax); ay = fmaf(vv.y, c, ay);
        az = fmaf(vv.z, c, az); aw = fmaf(vv.w, c, aw);
    }

    float rs = g_rinv_in[v];
    ((float4*)(g_msg + (size_t)v * D))[lane] =
        make_float4(ax * rs, ay * rs, az * rs, aw * rs);
}

// ---------------- GEMM: out[row] = g_msg[row] @ W + b -----------------------
// Block 256 threads, 32 rows/block. Static smem 48 KB (2 K-chunks of W + tile).
// TO_H: out = relu(.) * rinv_out[row] into g_h (feeds layer-2 gather pre-scaled)
template <bool TO_H>
__global__ void gemm_kernel(const float* __restrict__ W,
                            const float* __restrict__ b,
                            float* __restrict__ outp) {
    __shared__ float sW[64 * D];
    __shared__ float sIn[32 * D];

    int tid = threadIdx.x;
    int rowBase = blockIdx.x * 32;
    float* out = TO_H ? (float*)g_h : outp;

    // cooperative load of the 32x128 input tile (already fully scaled)
    float4* sIn4 = (float4*)sIn;
    #pragma unroll
    for (int i = 0; i < 4; i++) {
        int idx = tid + 256 * i;
        int lr = idx >> 5;
        int row = rowBase + lr;
        float4 v = make_float4(0.f, 0.f, 0.f, 0.f);
        if (row < N_NODES)
            v = ((const float4*)(g_msg + (size_t)row * D))[idx & 31];
        sIn4[idx] = v;
    }

    int ty = tid >> 5;                 // 0..7  -> 4 rows each
    int col0 = (tid & 31) * 4;         // 4 cols each
    int lr0 = ty * 4;

    float acc[4][4];
    float4 bv = *(const float4*)(b + col0);
    #pragma unroll
    for (int r = 0; r < 4; r++) {
        acc[r][0] = bv.x; acc[r][1] = bv.y; acc[r][2] = bv.z; acc[r][3] = bv.w;
    }

    const float4* W4 = (const float4*)W;
    float4* sW4 = (float4*)sW;

    #pragma unroll
    for (int kc = 0; kc < 2; kc++) {
        __syncthreads();
        #pragma unroll
        for (int i = 0; i < 8; i++)
            sW4[tid + 256 * i] = W4[kc * 2048 + tid + 256 * i];
        __syncthreads();

        #pragma unroll 4
        for (int k = 0; k < 64; k++) {
            float4 w = *(const float4*)(sW + k * D + col0);
            #pragma unroll
            for (int r = 0; r < 4; r++) {
                float a = sIn[(lr0 + r) * D + kc * 64 + k];
                acc[r][0] = fmaf(a, w.x, acc[r][0]);
                acc[r][1] = fmaf(a, w.y, acc[r][1]);
                acc[r][2] = fmaf(a, w.z, acc[r][2]);
                acc[r][3] = fmaf(a, w.w, acc[r][3]);
            }
        }
    }

    #pragma unroll
    for (int r = 0; r < 4; r++) {
        int row = rowBase + lr0 + r;
        if (row < N_NODES) {
            float4 o;
            if (TO_H) {
                float rs = g_rinv_out[row];   // pre-scale for layer-2 gather
                o = make_float4(fmaxf(acc[r][0], 0.f) * rs,
                                fmaxf(acc[r][1], 0.f) * rs,
                                fmaxf(acc[r][2], 0.f) * rs,
                                fmaxf(acc[r][3], 0.f) * rs);
            } else {
                o = make_float4(acc[r][0], acc[r][1], acc[r][2], acc[r][3]);
            }
            *(float4*)(out + (size_t)row * D + col0) = o;
        }
    }
}

// ---------------- launch ----------------------------------------------------
// Launches ONLY — no runtime API calls, no device-symbol addresses from host.

extern "C" void kernel_launch(void* const* d_in, const int* in_sizes, int n_in,
                              void* d_out, int out_size) {
    const float* x   = (const float*)d_in[0];
    const int*   src = (const int*)d_in[1];
    const int*   dst = (const int*)d_in[2];
    const float* W1  = (const float*)d_in[3];
    const float* b1  = (const float*)d_in[4];
    const float* W2  = (const float*)d_in[5];
    const float* b2  = (const float*)d_in[6];
    float* out = (float*)d_out;

    const int T = 256;
    int nodeBlocks = (N_NODES + T - 1) / T;
    int edgeBlocks = (N_EDGES + T - 1) / T;
    int aggBlocks  = (int)(((long long)N_NODES * 32 + T - 1) / T);
    int gemmBlocks = (N_NODES + 31) / 32;

    // CSR build (shared by both layers)
    zero_deg_kernel<<<nodeBlocks, T>>>();
    deg_kernel<<<edgeBlocks, T>>>(src, dst);
    rinv_kernel<<<nodeBlocks, T>>>();
    scan_kernel<<<1, 1024>>>();
    fill_kernel<<<edgeBlocks, T>>>(src, dst);

    // layer 1: msg = rinv_in * sum(x[src] * rinv_out[src]); h = relu(msg@W1+b1)*rinv_out
    agg_kernel<false><<<aggBlocks, T>>>(x);
    gemm_kernel<true><<<gemmBlocks, T>>>(W1, b1, nullptr);

    // layer 2: msg = rinv_in * sum(h[src]); out = msg@W2 + b2
    agg_kernel<true><<<aggBlocks, T>>>(nullptr);
    gemm_kernel<false><<<gemmBlocks, T>>>(W2, b2, out);
}

// round 6
// speedup vs baseline: 1.5909x; 1.4137x over previous
#include <cuda_runtime.h>

#define N_NODES 50000
#define D 128
#define N_EDGES 800000

// ---------------- scratch (device globals: no allocation allowed) ----------
__device__ __align__(16) float g_msg[N_NODES * D];  // aggregated (rinv_in-scaled)
__device__ __align__(16) float g_h[N_NODES * D];    // layer-1 act (rinv_out-scaled)
__device__ float g_rinv_out[N_NODES];
__device__ float g_rinv_in[N_NODES];
__device__ int   g_deg_out[N_NODES];
__device__ int   g_deg_in[N_NODES];
__device__ int   g_off[N_NODES];                    // CSR bucket start (unordered alloc)
__device__ int   g_cur[N_NODES];                    // fill cursors
__device__ int   g_esrc[N_EDGES];                   // src ids bucketed by dst
__device__ int   g_total;                           // bump allocator

// ---------------- graph preprocessing --------------------------------------

__global__ void zero_deg_kernel() {
    int i = blockIdx.x * blockDim.x + threadIdx.x;
    if (i < N_NODES) { g_deg_out[i] = 0; g_deg_in[i] = 0; }
    if (i == 0) g_total = 0;
}

// NOTE: indices are int32 (JAX x64 disabled => int32 despite jnp.int64 request)
__global__ void deg_kernel(const int* __restrict__ src,
                           const int* __restrict__ dst) {
    int e = blockIdx.x * blockDim.x + threadIdx.x;
    if (e < N_EDGES) {
        atomicAdd(&g_deg_out[src[e]], 1);
        atomicAdd(&g_deg_in[dst[e]], 1);
    }
}

__global__ void rinv_kernel() {
    int i = blockIdx.x * blockDim.x + threadIdx.x;
    if (i < N_NODES) {
        g_rinv_out[i] = rsqrtf((float)max(g_deg_out[i], 1));
        g_rinv_in[i]  = rsqrtf((float)max(g_deg_in[i], 1));
    }
}

// Parallel bucket allocation: block-local exclusive scan of deg_in over 256
// nodes + ONE global atomicAdd per block. Bucket order across blocks is
// arbitrary — aggregation only needs [off, off+deg) to be unique+contiguous.
__global__ void alloc_kernel() {
    __shared__ int s[256];
    __shared__ int base;
    int t = threadIdx.x;
    int i = blockIdx.x * 256 + t;
    int d = (i < N_NODES) ? g_deg_in[i] : 0;
    s[t] = d;
    __syncthreads();
    // Hillis-Steele inclusive scan (8 rounds)
    #pragma unroll
    for (int o = 1; o < 256; o <<= 1) {
        int v = (t >= o) ? s[t - o] : 0;
        __syncthreads();
        s[t] += v;
        __syncthreads();
    }
    if (t == 255) base = atomicAdd(&g_total, s[255]);
    __syncthreads();
    if (i < N_NODES) {
        int beg = base + s[t] - d;    // exclusive prefix + block base
        g_off[i] = beg;
        g_cur[i] = beg;
    }
}

__global__ void fill_kernel(const int* __restrict__ src,
                            const int* __restrict__ dst) {
    int e = blockIdx.x * blockDim.x + threadIdx.x;
    if (e < N_EDGES) {
        int pos = atomicAdd(&g_cur[dst[e]], 1);
        g_esrc[pos] = src[e];
    }
}

// ---------------- aggregation: one warp per node ----------------------------
// msg[v] = rinv_in[v] * sum_{e: dst=v} scale_e * in[src_e]
// Layer 1 (FROM_H=false): in = xin (harness pointer), scale_e = rinv_out[src_e]
// Layer 2 (FROM_H=true):  in = g_h (already rinv_out-scaled), scale_e = 1
template <bool FROM_H>
__global__ void agg_kernel(const float* __restrict__ xin) {
    int gtid = blockIdx.x * blockDim.x + threadIdx.x;
    int v = gtid >> 5;
    int lane = gtid & 31;
    if (v >= N_NODES) return;
    const float* in = FROM_H ? (const float*)g_h : xin;

    int beg = g_off[v];
    int end = beg + g_deg_in[v];
    float ax = 0.f, ay = 0.f, az = 0.f, aw = 0.f;

    int i = beg;
    for (; i + 4 <= end; i += 4) {
        int s0 = g_esrc[i + 0];
        int s1 = g_esrc[i + 1];
        int s2 = g_esrc[i + 2];
        int s3 = g_esrc[i + 3];
        float4 v0 = ((const float4*)(in + (size_t)s0 * D))[lane];
        float4 v1 = ((const float4*)(in + (size_t)s1 * D))[lane];
        float4 v2 = ((const float4*)(in + (size_t)s2 * D))[lane];
        float4 v3 = ((const float4*)(in + (size_t)s3 * D))[lane];
        if (!FROM_H) {
            float c0 = g_rinv_out[s0], c1 = g_rinv_out[s1];
            float c2 = g_rinv_out[s2], c3 = g_rinv_out[s3];
            ax = fmaf(v0.x, c0, fmaf(v1.x, c1, fmaf(v2.x, c2, fmaf(v3.x, c3, ax))));
            ay = fmaf(v0.y, c0, fmaf(v1.y, c1, fmaf(v2.y, c2, fmaf(v3.y, c3, ay))));
            az = fmaf(v0.z, c0, fmaf(v1.z, c1, fmaf(v2.z, c2, fmaf(v3.z, c3, az))));
            aw = fmaf(v0.w, c0, fmaf(v1.w, c1, fmaf(v2.w, c2, fmaf(v3.w, c3, aw))));
        } else {
            ax += v0.x + v1.x + v2.x + v3.x;
            ay += v0.y + v1.y + v2.y + v3.y;
            az += v0.z + v1.z + v2.z + v3.z;
            aw += v0.w + v1.w + v2.w + v3.w;
        }
    }
    for (; i < end; i++) {
        int s = g_esrc[i];
        float4 vv = ((const float4*)(in + (size_t)s * D))[lane];
        float c = FROM_H ? 1.f : g_rinv_out[s];
        ax = fmaf(vv.x, c, ax); ay = fmaf(vv.y, c, ay);
        az = fmaf(vv.z, c, az); aw = fmaf(vv.w, c, aw);
    }

    float rs = g_rinv_in[v];
    ((float4*)(g_msg + (size_t)v * D))[lane] =
        make_float4(ax * rs, ay * rs, az * rs, aw * rs);
}

// ---------------- GEMM: out[row] = g_msg[row] @ W + b -----------------------
// Block 256 threads, 32 rows/block. Static smem 48 KB (2 K-chunks of W + tile).
// TO_H: out = relu(.) * rinv_out[row] into g_h (feeds layer-2 gather pre-scaled)
template <bool TO_H>
__global__ void gemm_kernel(const float* __restrict__ W,
                            const float* __restrict__ b,
                            float* __restrict__ outp) {
    __shared__ float sW[64 * D];
    __shared__ float sIn[32 * D];

    int tid = threadIdx.x;
    int rowBase = blockIdx.x * 32;
    float* out = TO_H ? (float*)g_h : outp;

    // cooperative load of the 32x128 input tile (already fully scaled)
    float4* sIn4 = (float4*)sIn;
    #pragma unroll
    for (int i = 0; i < 4; i++) {
        int idx = tid + 256 * i;
        int lr = idx >> 5;
        int row = rowBase + lr;
        float4 v = make_float4(0.f, 0.f, 0.f, 0.f);
        if (row < N_NODES)
            v = ((const float4*)(g_msg + (size_t)row * D))[idx & 31];
        sIn4[idx] = v;
    }

    int ty = tid >> 5;                 // 0..7  -> 4 rows each
    int col0 = (tid & 31) * 4;         // 4 cols each
    int lr0 = ty * 4;

    float acc[4][4];
    float4 bv = *(const float4*)(b + col0);
    #pragma unroll
    for (int r = 0; r < 4; r++) {
        acc[r][0] = bv.x; acc[r][1] = bv.y; acc[r][2] = bv.z; acc[r][3] = bv.w;
    }

    const float4* W4 = (const float4*)W;
    float4* sW4 = (float4*)sW;

    #pragma unroll
    for (int kc = 0; kc < 2; kc++) {
        __syncthreads();
        #pragma unroll
        for (int i = 0; i < 8; i++)
            sW4[tid + 256 * i] = W4[kc * 2048 + tid + 256 * i];
        __syncthreads();

        #pragma unroll 4
        for (int k = 0; k < 64; k++) {
            float4 w = *(const float4*)(sW + k * D + col0);
            #pragma unroll
            for (int r = 0; r < 4; r++) {
                float a = sIn[(lr0 + r) * D + kc * 64 + k];
                acc[r][0] = fmaf(a, w.x, acc[r][0]);
                acc[r][1] = fmaf(a, w.y, acc[r][1]);
                acc[r][2] = fmaf(a, w.z, acc[r][2]);
                acc[r][3] = fmaf(a, w.w, acc[r][3]);
            }
        }
    }

    #pragma unroll
    for (int r = 0; r < 4; r++) {
        int row = rowBase + lr0 + r;
        if (row < N_NODES) {
            float4 o;
            if (TO_H) {
                float rs = g_rinv_out[row];   // pre-scale for layer-2 gather
                o = make_float4(fmaxf(acc[r][0], 0.f) * rs,
                                fmaxf(acc[r][1], 0.f) * rs,
                                fmaxf(acc[r][2], 0.f) * rs,
                                fmaxf(acc[r][3], 0.f) * rs);
            } else {
                o = make_float4(acc[r][0], acc[r][1], acc[r][2], acc[r][3]);
            }
            *(float4*)(out + (size_t)row * D + col0) = o;
        }
    }
}

// ---------------- launch ----------------------------------------------------
// Launches ONLY — no runtime API calls, no device-symbol addresses from host.

extern "C" void kernel_launch(void* const* d_in, const int* in_sizes, int n_in,
                              void* d_out, int out_size) {
    const float* x   = (const float*)d_in[0];
    const int*   src = (const int*)d_in[1];
    const int*   dst = (const int*)d_in[2];
    const float* W1  = (const float*)d_in[3];
    const float* b1  = (const float*)d_in[4];
    const float* W2  = (const float*)d_in[5];
    const float* b2  = (const float*)d_in[6];
    float* out = (float*)d_out;

    const int T = 256;
    int nodeBlocks = (N_NODES + T - 1) / T;
    int edgeBlocks = (N_EDGES + T - 1) / T;
    int aggBlocks  = (int)(((long long)N_NODES * 32 + T - 1) / T);
    int gemmBlocks = (N_NODES + 31) / 32;

    // CSR build (shared by both layers)
    zero_deg_kernel<<<nodeBlocks, T>>>();
    deg_kernel<<<edgeBlocks, T>>>(src, dst);
    rinv_kernel<<<nodeBlocks, T>>>();
    alloc_kernel<<<nodeBlocks, T>>>();
    fill_kernel<<<edgeBlocks, T>>>(src, dst);

    // layer 1: msg = rinv_in * sum(x[src] * rinv_out[src]); h = relu(msg@W1+b1)*rinv_out
    agg_kernel<false><<<aggBlocks, T>>>(x);
    gemm_kernel<true><<<gemmBlocks, T>>>(W1, b1, nullptr);

    // layer 2: msg = rinv_in * sum(h[src]); out = msg@W2 + b2
    agg_kernel<true><<<aggBlocks, T>>>(nullptr);
    gemm_kernel<false><<<gemmBlocks, T>>>(W2, b2, out);
}

// round 7
// speedup vs baseline: 2.1290x; 1.3382x over previous
#include <cuda_runtime.h>

#define N_NODES 50000
#define D 128
#define N_EDGES 800000

// ---------------- scratch (device globals: no allocation allowed) ----------
__device__ __align__(16) float g_msg[N_NODES * D];  // aggregated (rinv_in-scaled)
__device__ __align__(16) float g_h[N_NODES * D];    // layer-1 act (rinv_out-scaled)
__device__ float g_rinv_out[N_NODES];
__device__ float g_rinv_in[N_NODES];
__device__ int   g_deg_out[N_NODES];
__device__ int   g_deg_in[N_NODES];
__device__ int   g_off[N_NODES];                    // CSR bucket start (unordered alloc)
__device__ int   g_cur[N_NODES];                    // fill cursors
__device__ int   g_esrc[N_EDGES];                   // src ids bucketed by dst
__device__ int   g_total;                           // bump allocator

// ---------------- graph preprocessing --------------------------------------

__global__ void zero_deg_kernel() {
    int i = blockIdx.x * blockDim.x + threadIdx.x;
    if (i < N_NODES) { g_deg_out[i] = 0; g_deg_in[i] = 0; }
    if (i == 0) g_total = 0;
}

// NOTE: indices are int32 (JAX x64 disabled => int32 despite jnp.int64 request)
__global__ void deg_kernel(const int* __restrict__ src,
                           const int* __restrict__ dst) {
    int e = blockIdx.x * blockDim.x + threadIdx.x;
    if (e < N_EDGES) {
        atomicAdd(&g_deg_out[src[e]], 1);
        atomicAdd(&g_deg_in[dst[e]], 1);
    }
}

__global__ void rinv_kernel() {
    int i = blockIdx.x * blockDim.x + threadIdx.x;
    if (i < N_NODES) {
        g_rinv_out[i] = rsqrtf((float)max(g_deg_out[i], 1));
        g_rinv_in[i]  = rsqrtf((float)max(g_deg_in[i], 1));
    }
}

// Parallel bucket allocation: block-local exclusive scan of deg_in over 256
// nodes + ONE global atomicAdd per block. Bucket order across blocks is
// arbitrary — aggregation only needs [off, off+deg) to be unique+contiguous.
__global__ void alloc_kernel() {
    __shared__ int s[256];
    __shared__ int base;
    int t = threadIdx.x;
    int i = blockIdx.x * 256 + t;
    int d = (i < N_NODES) ? g_deg_in[i] : 0;
    s[t] = d;
    __syncthreads();
    #pragma unroll
    for (int o = 1; o < 256; o <<= 1) {
        int v = (t >= o) ? s[t - o] : 0;
        __syncthreads();
        s[t] += v;
        __syncthreads();
    }
    if (t == 255) base = atomicAdd(&g_total, s[255]);
    __syncthreads();
    if (i < N_NODES) {
        int beg = base + s[t] - d;
        g_off[i] = beg;
        g_cur[i] = beg;
    }
}

__global__ void fill_kernel(const int* __restrict__ src,
                            const int* __restrict__ dst) {
    int e = blockIdx.x * blockDim.x + threadIdx.x;
    if (e < N_EDGES) {
        int pos = atomicAdd(&g_cur[dst[e]], 1);
        g_esrc[pos] = src[e];
    }
}

// ---------------- aggregation: one warp per node ----------------------------
template <bool FROM_H>
__global__ void agg_kernel(const float* __restrict__ xin) {
    int gtid = blockIdx.x * blockDim.x + threadIdx.x;
    int v = gtid >> 5;
    int lane = gtid & 31;
    if (v >= N_NODES) return;
    const float* in = FROM_H ? (const float*)g_h : xin;

    int beg = g_off[v];
    int end = beg + g_deg_in[v];
    float ax = 0.f, ay = 0.f, az = 0.f, aw = 0.f;

    int i = beg;
    for (; i + 4 <= end; i += 4) {
        int s0 = g_esrc[i + 0];
        int s1 = g_esrc[i + 1];
        int s2 = g_esrc[i + 2];
        int s3 = g_esrc[i + 3];
        float4 v0 = ((const float4*)(in + (size_t)s0 * D))[lane];
        float4 v1 = ((const float4*)(in + (size_t)s1 * D))[lane];
        float4 v2 = ((const float4*)(in + (size_t)s2 * D))[lane];
        float4 v3 = ((const float4*)(in + (size_t)s3 * D))[lane];
        if (!FROM_H) {
            float c0 = g_rinv_out[s0], c1 = g_rinv_out[s1];
            float c2 = g_rinv_out[s2], c3 = g_rinv_out[s3];
            ax = fmaf(v0.x, c0, fmaf(v1.x, c1, fmaf(v2.x, c2, fmaf(v3.x, c3, ax))));
            ay = fmaf(v0.y, c0, fmaf(v1.y, c1, fmaf(v2.y, c2, fmaf(v3.y, c3, ay))));
            az = fmaf(v0.z, c0, fmaf(v1.z, c1, fmaf(v2.z, c2, fmaf(v3.z, c3, az))));
            aw = fmaf(v0.w, c0, fmaf(v1.w, c1, fmaf(v2.w, c2, fmaf(v3.w, c3, aw))));
        } else {
            ax += v0.x + v1.x + v2.x + v3.x;
            ay += v0.y + v1.y + v2.y + v3.y;
            az += v0.z + v1.z + v2.z + v3.z;
            aw += v0.w + v1.w + v2.w + v3.w;
        }
    }
    for (; i < end; i++) {
        int s = g_esrc[i];
        float4 vv = ((const float4*)(in + (size_t)s * D))[lane];
        float c = FROM_H ? 1.f : g_rinv_out[s];
        ax = fmaf(vv.x, c, ax); ay = fmaf(vv.y, c, ay);
        az = fmaf(vv.z, c, az); aw = fmaf(vv.w, c, aw);
    }

    float rs = g_rinv_in[v];
    ((float4*)(g_msg + (size_t)v * D))[lane] =
        make_float4(ax * rs, ay * rs, az * rs, aw * rs);
}

// ---------------- tensor-core GEMM (tf32 mma.sync) --------------------------
// out[row] = g_msg[row] @ W + b ; TO_H: relu + rinv_out scale into g_h.
// Block 256 threads (8 warps): tile BM=64 rows x BN=128 cols, K=128 chunked 16.
// Warp tile: 16 rows x 64 cols (warp_m = wid>>1, warp_n = wid&1), 8 n-tiles.
// smem strides padded for conflict-free fragment loads:
//   sIn stride 132 words (132%32==4), sW stride 136 words (136%32==8).

#define SIN_S 132
#define SW_S  136

__device__ __forceinline__ float f2tf32(float f) {
    unsigned u;
    asm("cvt.rna.tf32.f32 %0, %1;" : "=r"(u) : "f"(f));
    return __uint_as_float(u);
}

template <bool TO_H>
__global__ void gemm_tc_kernel(const float* __restrict__ W,
                               const float* __restrict__ b,
                               float* __restrict__ outp) {
    __shared__ float sIn[64 * SIN_S];   // tf32-converted input tile [64][128]
    __shared__ float sW[16 * SW_S];     // tf32-converted W chunk   [16][128]

    int tid = threadIdx.x;
    int wid = tid >> 5;
    int lane = tid & 31;
    int g = lane >> 2;                  // group id 0..7
    int t = lane & 3;                   // thread-in-group 0..3
    int warp_m = wid >> 1;              // 0..3
    int warp_n = wid & 1;               // 0..1
    int rowBase = blockIdx.x * 64;
    float* out = TO_H ? (float*)g_h : outp;

    // ---- fill sIn: 64 rows x 128 cols, tf32-converted, zero-padded tail ----
    #pragma unroll
    for (int i = 0; i < 8; i++) {
        int idx = tid + 256 * i;        // float4 index, 2048 total
        int lr = idx >> 5;              // local row
        int k4 = idx & 31;              // float4 col
        int row = rowBase + lr;
        float4 v = make_float4(0.f, 0.f, 0.f, 0.f);
        if (row < N_NODES)
            v = ((const float4*)(g_msg + (size_t)row * D))[k4];
        float4 c = make_float4(f2tf32(v.x), f2tf32(v.y), f2tf32(v.z), f2tf32(v.w));
        *(float4*)&sIn[lr * SIN_S + k4 * 4] = c;
    }

    float acc[8][4];
    #pragma unroll
    for (int nt = 0; nt < 8; nt++)
        #pragma unroll
        for (int r = 0; r < 4; r++) acc[nt][r] = 0.f;

    int r0 = warp_m * 16 + g;           // local A row for fragments

    #pragma unroll
    for (int kc = 0; kc < 8; kc++) {    // 8 chunks of 16 k
        __syncthreads();                // protect sW reuse (first iter: sIn ready)
        // fill sW chunk: rows [kc*16, +16) of W, 512 float4, 2 per thread
        #pragma unroll
        for (int i = 0; i < 2; i++) {
            int idx = tid + 256 * i;
            int wr = idx >> 5;          // 0..15
            int k4 = idx & 31;
            float4 v = ((const float4*)(W + (size_t)(kc * 16 + wr) * D))[k4];
            float4 c = make_float4(f2tf32(v.x), f2tf32(v.y), f2tf32(v.z), f2tf32(v.w));
            *(float4*)&sW[wr * SW_S + k4 * 4] = c;
        }
        __syncthreads();

        #pragma unroll
        for (int ks = 0; ks < 2; ks++) {    // 2 k-steps of 8 per chunk
            int kb = kc * 16 + ks * 8;      // global k base (for sIn)
            int kq = ks * 8;                // local k base (for sW)
            unsigned a0 = __float_as_uint(sIn[r0 * SIN_S + kb + t]);
            unsigned a1 = __float_as_uint(sIn[(r0 + 8) * SIN_S + kb + t]);
            unsigned a2 = __float_as_uint(sIn[r0 * SIN_S + kb + t + 4]);
            unsigned a3 = __float_as_uint(sIn[(r0 + 8) * SIN_S + kb + t + 4]);
            #pragma unroll
            for (int nt = 0; nt < 8; nt++) {
                int n = warp_n * 64 + nt * 8 + g;
                unsigned b0 = __float_as_uint(sW[(kq + t) * SW_S + n]);
                unsigned b1 = __float_as_uint(sW[(kq + t + 4) * SW_S + n]);
                asm volatile(
                    "mma.sync.aligned.m16n8k8.row.col.f32.tf32.tf32.f32 "
                    "{%0,%1,%2,%3}, {%4,%5,%6,%7}, {%8,%9}, {%0,%1,%2,%3};"
                    : "+f"(acc[nt][0]), "+f"(acc[nt][1]),
                      "+f"(acc[nt][2]), "+f"(acc[nt][3])
                    : "r"(a0), "r"(a1), "r"(a2), "r"(a3), "r"(b0), "r"(b1));
            }
        }
    }

    // ---- epilogue: bias (+ relu*rinv_out for layer 1), write float2 pairs ----
    #pragma unroll
    for (int nt = 0; nt < 8; nt++) {
        int col = warp_n * 64 + nt * 8 + t * 2;
        float2 bv = *(const float2*)(b + col);
        int row0 = rowBase + warp_m * 16 + g;
        int row1 = row0 + 8;
        if (row0 < N_NODES) {
            float v0 = acc[nt][0] + bv.x, v1 = acc[nt][1] + bv.y;
            if (TO_H) {
                float rs = g_rinv_out[row0];
                v0 = fmaxf(v0, 0.f) * rs; v1 = fmaxf(v1, 0.f) * rs;
            }
            *(float2*)(out + (size_t)row0 * D + col) = make_float2(v0, v1);
        }
        if (row1 < N_NODES) {
            float v2 = acc[nt][2] + bv.x, v3 = acc[nt][3] + bv.y;
            if (TO_H) {
                float rs = g_rinv_out[row1];
                v2 = fmaxf(v2, 0.f) * rs; v3 = fmaxf(v3, 0.f) * rs;
            }
            *(float2*)(out + (size_t)row1 * D + col) = make_float2(v2, v3);
        }
    }
}

// ---------------- launch ----------------------------------------------------
// Launches ONLY — no runtime API calls, no device-symbol addresses from host.

extern "C" void kernel_launch(void* const* d_in, const int* in_sizes, int n_in,
                              void* d_out, int out_size) {
    const float* x   = (const float*)d_in[0];
    const int*   src = (const int*)d_in[1];
    const int*   dst = (const int*)d_in[2];
    const float* W1  = (const float*)d_in[3];
    const float* b1  = (const float*)d_in[4];
    const float* W2  = (const float*)d_in[5];
    const float* b2  = (const float*)d_in[6];
    float* out = (float*)d_out;

    const int T = 256;
    int nodeBlocks = (N_NODES + T - 1) / T;
    int edgeBlocks = (N_EDGES + T - 1) / T;
    int aggBlocks  = (int)(((long long)N_NODES * 32 + T - 1) / T);
    int gemmBlocks = (N_NODES + 63) / 64;

    // CSR build (shared by both layers)
    zero_deg_kernel<<<nodeBlocks, T>>>();
    deg_kernel<<<edgeBlocks, T>>>(src, dst);
    rinv_kernel<<<nodeBlocks, T>>>();
    alloc_kernel<<<nodeBlocks, T>>>();
    fill_kernel<<<edgeBlocks, T>>>(src, dst);

    // layer 1
    agg_kernel<false><<<aggBlocks, T>>>(x);
    gemm_tc_kernel<true><<<gemmBlocks, T>>>(W1, b1, nullptr);

    // layer 2
    agg_kernel<true><<<aggBlocks, T>>>(nullptr);
    gemm_tc_kernel<false><<<gemmBlocks, T>>>(W2, b2, out);
}